// round 16
// baseline (speedup 1.0000x reference)
#include <cuda_runtime.h>
#include <cuda_fp16.h>
#include <math.h>
#include <stdint.h>

#define B_ 32
#define D_ 64
#define H_ 8
#define N_ 4096
#define L_ 12
#define DK_ 8
#define NL_ 49152
#define SCALE 0.3535533905932738f
#define CL2E 0.5101185143353461f   // SCALE * log2(e)
#define K2SPLIT 8

// ---- scratch ----
__device__ __half  g_q16[(size_t)B_ * NL_ * 64];
__device__ __half  g_v16[(size_t)B_ * NL_ * 64];
__device__ __half  g_keysm16[(size_t)H_ * L_ * N_ * DK_];
__device__ float   g_kv[B_ * H_ * L_ * DK_ * DK_];
__device__ float   g_kvp[K2SPLIT * B_ * H_ * L_ * DK_ * DK_];
__device__ __half2 g_wb[(size_t)D_ * NL_];

__device__ __forceinline__ void mma16816(float* c, const uint32_t* a,
                                         uint32_t b0, uint32_t b1) {
    asm volatile(
        "mma.sync.aligned.m16n8k16.row.col.f32.f16.f16.f32 "
        "{%0,%1,%2,%3}, {%4,%5,%6,%7}, {%8,%9}, {%0,%1,%2,%3};\n"
        : "+f"(c[0]), "+f"(c[1]), "+f"(c[2]), "+f"(c[3])
        : "r"(a[0]), "r"(a[1]), "r"(a[2]), "r"(a[3]), "r"(b0), "r"(b1));
}

__device__ __forceinline__ uint32_t su(const void* p) {
    return (uint32_t)__cvta_generic_to_shared(p);
}

__device__ __forceinline__ void cp16(uint32_t saddr, const void* gptr) {
    asm volatile("cp.async.cg.shared.global [%0], [%1], 16;\n"
                 :: "r"(saddr), "l"(gptr));
}
#define CP_COMMIT() asm volatile("cp.async.commit_group;\n" ::: "memory")
#define CP_WAIT1()  asm volatile("cp.async.wait_group 1;\n" ::: "memory")
#define CP_WAIT0()  asm volatile("cp.async.wait_group 0;\n" ::: "memory")

#define LDSM4(r0, r1, r2, r3, addr)                                        \
    asm volatile("ldmatrix.sync.aligned.m8n8.x4.shared.b16 {%0,%1,%2,%3}, [%4];" \
                 : "=r"(r0), "=r"(r1), "=r"(r2), "=r"(r3) : "r"(addr))

#define STSM4T(addr, r0, r1, r2, r3)                                       \
    asm volatile("stmatrix.sync.aligned.m8n8.x4.trans.shared.b16 [%0], {%1,%2,%3,%4};" \
                 :: "r"(addr), "r"(r0), "r"(r1), "r"(r2), "r"(r3))

__device__ __forceinline__ uint32_t h2u(__half2 h) {
    return *reinterpret_cast<uint32_t*>(&h);
}

// ============================================================
// K0: key_sm = softmax(memory * scale, axis=-1) -> fp16
// ============================================================
__global__ void k0_keysm(const float* __restrict__ memin) {
    int i = blockIdx.x * blockDim.x + threadIdx.x;
    if (i >= H_ * L_ * N_) return;
    const float4 f0 = ((const float4*)memin)[(size_t)i * 2];
    const float4 f1 = ((const float4*)memin)[(size_t)i * 2 + 1];
    float v[8] = {f0.x, f0.y, f0.z, f0.w, f1.x, f1.y, f1.z, f1.w};
    float m = -1e30f;
#pragma unroll
    for (int k = 0; k < 8; k++) { v[k] *= SCALE; m = fmaxf(m, v[k]); }
    float s = 0.f;
#pragma unroll
    for (int k = 0; k < 8; k++) { v[k] = __expf(v[k] - m); s += v[k]; }
    const float inv = 1.f / s;
    uint4 u;
    u.x = h2u(__floats2half2_rn(v[0] * inv, v[1] * inv));
    u.y = h2u(__floats2half2_rn(v[2] * inv, v[3] * inv));
    u.z = h2u(__floats2half2_rn(v[4] * inv, v[5] * inv));
    u.w = h2u(__floats2half2_rn(v[6] * inv, v[7] * inv));
    ((uint4*)g_keysm16)[i] = u;
}

// ============================================================
// K0W: pack (weight, bias) -> half2
// ============================================================
__global__ void k0_wb(const float* __restrict__ weight,
                      const float* __restrict__ bias) {
    const int i = blockIdx.x * 256 + threadIdx.x;
    if (i >= D_ * NL_ / 4) return;
    const float4 w = ((const float4*)weight)[i];
    const float4 bi = ((const float4*)bias)[i];
    uint4 u;
    u.x = h2u(__floats2half2_rn(w.x, bi.x));
    u.y = h2u(__floats2half2_rn(w.y, bi.y));
    u.z = h2u(__floats2half2_rn(w.z, bi.z));
    u.w = h2u(__floats2half2_rn(w.w, bi.w));
    ((uint4*)g_wb)[i] = u;
}

// ============================================================
// K1 (HMMA+LDSM+STSM, 4 tiles/block): [q;v] = [Wq;Wv] @ x  (R14)
// ============================================================
#define P72 72
#define QVP 136
#define K1_XS_OFF  (128 * P72 * 2)
#define K1_SQV_OFF (K1_XS_OFF + 128 * P72 * 2)
#define K1_SMEM    (K1_SQV_OFF + 128 * QVP * 2)
__global__ __launch_bounds__(256, 3)
void k1_qv(const float* __restrict__ x,  const float* __restrict__ wq,
           const float* __restrict__ bq, const float* __restrict__ wv,
           const float* __restrict__ bv) {
    extern __shared__ char sm1[];
    __half* sW  = (__half*)sm1;
    __half* xs  = (__half*)(sm1 + K1_XS_OFF);
    __half* sQV = (__half*)(sm1 + K1_SQV_OFF);

    const int t = threadIdx.x;
    const int b = blockIdx.y;

    for (int i = t; i < 512; i += 256) {
        const int row = i >> 3, seg = i & 7;
        const float4 f0 = *(const float4*)(wq + row * 64 + seg * 8);
        const float4 f1 = *(const float4*)(wq + row * 64 + seg * 8 + 4);
        uint4 u;
        u.x = h2u(__floats2half2_rn(f0.x, f0.y));
        u.y = h2u(__floats2half2_rn(f0.z, f0.w));
        u.z = h2u(__floats2half2_rn(f1.x, f1.y));
        u.w = h2u(__floats2half2_rn(f1.z, f1.w));
        *(uint4*)&sW[row * P72 + seg * 8] = u;
        const float4 g0 = *(const float4*)(wv + row * 64 + seg * 8);
        const float4 g1 = *(const float4*)(wv + row * 64 + seg * 8 + 4);
        u.x = h2u(__floats2half2_rn(g0.x, g0.y));
        u.y = h2u(__floats2half2_rn(g0.z, g0.w));
        u.z = h2u(__floats2half2_rn(g1.x, g1.y));
        u.w = h2u(__floats2half2_rn(g1.z, g1.w));
        *(uint4*)&sW[(64 + row) * P72 + seg * 8] = u;
    }

    const int wid = t >> 5, lane = t & 31;
    const int cg = wid;

    float bqC[8];
    __half2 bv2[4];
#pragma unroll
    for (int j = 0; j < 8; j++) bqC[j] = bq[cg * 8 + j] * CL2E;
#pragma unroll
    for (int j = 0; j < 4; j++)
        bv2[j] = __floats2half2_rn(bv[cg * 8 + 2 * j], bv[cg * 8 + 2 * j + 1]);
    const __half2 hzero = __float2half2_rn(0.f);

    const int mat = lane >> 3, mrow = lane & 7;
    const uint32_t stbase =
        su(sQV + ((mat >> 1) * 8 + mrow) * QVP + wid * 16 + (mat & 1) * 8);
    const int brow = lane & 7, bseg = lane >> 3;

    bool haveA = false;
    uint32_t a[4][4];

    for (int tile = 0; tile < 4; tile++) {
        const int base = blockIdx.x * 512 + tile * 128;

        {
            const int pos = t & 127;
            const int d0  = (t >> 7) * 32;
            const float* xb = x + (size_t)b * D_ * NL_ + base + pos;
            uint32_t pk[16];
#pragma unroll 4
            for (int dd = 0; dd < 32; dd += 2) {
                float x0 = xb[(size_t)(d0 + dd) * NL_];
                float x1 = xb[(size_t)(d0 + dd + 1) * NL_];
                pk[dd >> 1] = h2u(__floats2half2_rn(x0, x1));
            }
            uint4* dst = (uint4*)&xs[pos * P72 + d0];
#pragma unroll
            for (int s = 0; s < 4; s++)
                dst[s] = make_uint4(pk[4*s], pk[4*s+1], pk[4*s+2], pk[4*s+3]);
        }
        __syncthreads();

        if (!haveA) {
            const uint32_t abase =
                su(sW + (wid * 16 + (lane & 15)) * P72 + (lane >> 4) * 8);
#pragma unroll
            for (int kt = 0; kt < 4; kt++)
                LDSM4(a[kt][0], a[kt][1], a[kt][2], a[kt][3], abase + kt * 32);
            haveA = true;
        }

#pragma unroll
        for (int pass = 0; pass < 2; pass++) {
            float acc[8][4];
#pragma unroll
            for (int nt = 0; nt < 8; nt++)
#pragma unroll
                for (int i = 0; i < 4; i++) acc[nt][i] = 0.f;

#pragma unroll
            for (int nt = 0; nt < 8; nt++) {
                const int ntg = pass * 8 + nt;
                const uint32_t bbase = su(xs + (ntg * 8 + brow) * P72 + bseg * 8);
#pragma unroll
                for (int kg = 0; kg < 2; kg++) {
                    uint32_t r0, r1, r2, r3;
                    LDSM4(r0, r1, r2, r3, bbase + kg * 64);
                    mma16816(acc[nt], a[kg * 2],     r0, r1);
                    mma16816(acc[nt], a[kg * 2 + 1], r2, r3);
                }
            }
#pragma unroll
            for (int j = 0; j < 4; j++) {
                const int nt0 = 2 * j;
                const uint32_t addr = stbase + (uint32_t)((pass * 8 + nt0) * 8 * QVP * 2);
                const uint32_t r0 = h2u(__floats2half2_rn(acc[nt0][0],     acc[nt0][1]));
                const uint32_t r1 = h2u(__floats2half2_rn(acc[nt0][2],     acc[nt0][3]));
                const uint32_t r2 = h2u(__floats2half2_rn(acc[nt0+1][0], acc[nt0+1][1]));
                const uint32_t r3 = h2u(__floats2half2_rn(acc[nt0+1][2], acc[nt0+1][3]));
                STSM4T(addr, r0, r1, r2, r3);
            }
        }
        __syncthreads();

#pragma unroll
        for (int i = 0; i < 4; i++) {
            const int pos = lane + 32 * i;
            const __half* row = sQV + pos * QVP;
            uint4 qraw = *(const uint4*)(row + cg * 8);
            uint4 vraw = *(const uint4*)(row + 64 + cg * 8);

            float e[8];
            {
                float2 f;
                f = __half22float2(*reinterpret_cast<__half2*>(&qraw.x)); e[0]=f.x; e[1]=f.y;
                f = __half22float2(*reinterpret_cast<__half2*>(&qraw.y)); e[2]=f.x; e[3]=f.y;
                f = __half22float2(*reinterpret_cast<__half2*>(&qraw.z)); e[4]=f.x; e[5]=f.y;
                f = __half22float2(*reinterpret_cast<__half2*>(&qraw.w)); e[6]=f.x; e[7]=f.y;
            }
            float s = 0.f;
#pragma unroll
            for (int j = 0; j < 8; j++) {
                float aa = fmaf(e[j], CL2E, bqC[j]);
                aa = fmaxf(aa, 0.f);
                e[j] = exp2f(aa);
                s += e[j];
            }
            const float inv = __fdividef(1.f, s);

            uint4 qu, vu;
            qu.x = h2u(__floats2half2_rn(e[0] * inv, e[1] * inv));
            qu.y = h2u(__floats2half2_rn(e[2] * inv, e[3] * inv));
            qu.z = h2u(__floats2half2_rn(e[4] * inv, e[5] * inv));
            qu.w = h2u(__floats2half2_rn(e[6] * inv, e[7] * inv));

            vu.x = h2u(__hmax2(__hadd2(*reinterpret_cast<__half2*>(&vraw.x), bv2[0]), hzero));
            vu.y = h2u(__hmax2(__hadd2(*reinterpret_cast<__half2*>(&vraw.y), bv2[1]), hzero));
            vu.z = h2u(__hmax2(__hadd2(*reinterpret_cast<__half2*>(&vraw.z), bv2[2]), hzero));
            vu.w = h2u(__hmax2(__hadd2(*reinterpret_cast<__half2*>(&vraw.w), bv2[3]), hzero));

            const size_t ob = ((size_t)b * NL_ + base + pos) * 64 + cg * 8;
            *(uint4*)&g_q16[ob] = qu;
            *(uint4*)&g_v16[ob] = vu;
        }
        __syncthreads();
    }
}

// ============================================================
// K2: split-K (8) cp.async double-buffered; occupancy 4.
// ============================================================
#define K2_NCH 64
#define K2_KBUF 6144
#define K2_VBUF 6240
#define K2_V_OFF (2 * K2_KBUF)
#define K2_SMEM ((2 * K2_KBUF + 2 * K2_VBUF) * 2)
__global__ __launch_bounds__(192, 4)
void k2_kv() {
    extern __shared__ __half sm2[];
    __half* sK = sm2;
    __half* sV = sm2 + K2_V_OFF;

    const int t = threadIdx.x;
    const int h = blockIdx.x;
    const int b = blockIdx.y;
    const int sp = blockIdx.z;
    const int s = t & 15;
    const int l = t >> 4;

    const int nlo = sp * (N_ / K2SPLIT);
    const int nchunks = (N_ / K2SPLIT) / K2_NCH;

    int kll[4], knn[4], vll[4], vnn[4];
#pragma unroll
    for (int j = 0; j < 4; j++) {
        const int i = t + j * 192;
        kll[j] = i >> 6;  knn[j] = i & 63;
        vll[j] = i % 12;  vnn[j] = i / 12;
    }

    auto prefetch = [&](int n0, int buf) {
#pragma unroll
        for (int j = 0; j < 4; j++) {
            cp16(su(sK + buf * K2_KBUF + (kll[j] * 64 + knn[j]) * 8),
                 &g_keysm16[((size_t)(h * 12 + kll[j]) * N_ + n0 + knn[j]) * 8]);
        }
#pragma unroll
        for (int j = 0; j < 4; j++) {
            const int pos = (n0 + vnn[j]) * 12 + vll[j];
            cp16(su(sV + buf * K2_VBUF + (vll[j] * 65 + vnn[j]) * 8),
                 &g_v16[((size_t)b * NL_ + pos) * 64 + h * 8]);
        }
    };

    float acc[8][8];
#pragma unroll
    for (int xx = 0; xx < 8; xx++)
#pragma unroll
        for (int yy = 0; yy < 8; yy++) acc[xx][yy] = 0.f;

    prefetch(nlo, 0);
    CP_COMMIT();

    for (int c = 0; c < nchunks; c++) {
        if (c + 1 < nchunks) {
            prefetch(nlo + (c + 1) * K2_NCH, (c + 1) & 1);
            CP_COMMIT();
            CP_WAIT1();
        } else {
            CP_WAIT0();
        }
        __syncthreads();

        const __half* bK = sK + (c & 1) * K2_KBUF;
        const __half* bV = sV + (c & 1) * K2_VBUF;

#pragma unroll
        for (int p = 0; p < 4; p++) {
            const int nn = s + 16 * p;
            float kf[8], vf[8];
            uint4 ku = *(const uint4*)(bK + (l * 64 + nn) * 8);
            uint4 vu = *(const uint4*)(bV + (l * 65 + nn) * 8);
            {
                float2 f;
                f = __half22float2(*reinterpret_cast<__half2*>(&ku.x)); kf[0]=f.x; kf[1]=f.y;
                f = __half22float2(*reinterpret_cast<__half2*>(&ku.y)); kf[2]=f.x; kf[3]=f.y;
                f = __half22float2(*reinterpret_cast<__half2*>(&ku.z)); kf[4]=f.x; kf[5]=f.y;
                f = __half22float2(*reinterpret_cast<__half2*>(&ku.w)); kf[6]=f.x; kf[7]=f.y;
                f = __half22float2(*reinterpret_cast<__half2*>(&vu.x)); vf[0]=f.x; vf[1]=f.y;
                f = __half22float2(*reinterpret_cast<__half2*>(&vu.y)); vf[2]=f.x; vf[3]=f.y;
                f = __half22float2(*reinterpret_cast<__half2*>(&vu.z)); vf[4]=f.x; vf[5]=f.y;
                f = __half22float2(*reinterpret_cast<__half2*>(&vu.w)); vf[6]=f.x; vf[7]=f.y;
            }
#pragma unroll
            for (int xx = 0; xx < 8; xx++)
#pragma unroll
                for (int yy = 0; yy < 8; yy++) acc[xx][yy] += kf[xx] * vf[yy];
        }
        __syncthreads();
    }

#pragma unroll
    for (int xx = 0; xx < 8; xx++)
#pragma unroll
        for (int yy = 0; yy < 8; yy++) {
            float v_ = acc[xx][yy];
            v_ += __shfl_xor_sync(0xffffffffu, v_, 1);
            v_ += __shfl_xor_sync(0xffffffffu, v_, 2);
            v_ += __shfl_xor_sync(0xffffffffu, v_, 4);
            v_ += __shfl_xor_sync(0xffffffffu, v_, 8);
            acc[xx][yy] = v_;
        }
    if (s == 0) {
        float* dst = g_kvp + (size_t)sp * (B_ * H_ * L_ * 64) +
                     (((size_t)(b * 8 + h) * 12 + l) * 64);
#pragma unroll
        for (int xx = 0; xx < 8; xx++)
#pragma unroll
            for (int yy = 0; yy < 8; yy++) dst[xx * 8 + yy] = acc[xx][yy];
    }
}

__global__ void k2r_reduce() {
    const int i = blockIdx.x * 256 + threadIdx.x;
    const int S = B_ * H_ * L_ * 64;
    if (i >= S) return;
    float s = 0.f;
#pragma unroll
    for (int sp = 0; sp < K2SPLIT; sp++) s += g_kvp[i + (size_t)sp * S];
    g_kv[i] = s;
}

// ============================================================
// K3 (HMMA, 8 tiles/block): phase A half2 (R14 body); wb16 epilogue.
// ============================================================
#define KVH_PITCH 552
#define K3_KVH_OFF (64 * P72 * 2)
#define K3_YS_OFF  (K3_KVH_OFF + 12 * KVH_PITCH * 2)
#define K3_SMEM    (K3_YS_OFF + 128 * P72 * 2)
__global__ __launch_bounds__(256, 3)
void k3_out(const float* __restrict__ wc, const float* __restrict__ bc,
            float* __restrict__ out) {
    extern __shared__ char sm3[];
    __half* sWc = (__half*)sm3;
    __half* kvh = (__half*)(sm3 + K3_KVH_OFF);
    __half* ys  = (__half*)(sm3 + K3_YS_OFF);

    const int t = threadIdx.x;
    const int b = blockIdx.x;

    for (int i = t; i < 512; i += 256) {
        const int row = i >> 3, seg = i & 7;
        const float4 f0 = *(const float4*)(wc + row * 64 + seg * 8);
        const float4 f1 = *(const float4*)(wc + row * 64 + seg * 8 + 4);
        uint4 u;
        u.x = h2u(__floats2half2_rn(f0.x, f0.y));
        u.y = h2u(__floats2half2_rn(f0.z, f0.w));
        u.z = h2u(__floats2half2_rn(f1.x, f1.y));
        u.w = h2u(__floats2half2_rn(f1.z, f1.w));
        *(uint4*)&sWc[row * P72 + seg * 8] = u;
    }
    for (int i = t; i < 3072; i += 256) {
        const int idx = i * 2;
        const float2 f = *(const float2*)(g_kv + (size_t)b * 6144 + idx);
        const int h = idx / 768, r = idx % 768, l = r >> 6, xy = r & 63;
        *(__half2*)&kvh[l * KVH_PITCH + h * 64 + xy] = __floats2half2_rn(f.x, f.y);
    }
    __syncthreads();

    const int lane = t & 31, cg = t >> 5;
    const int wid = t >> 5;
    const int g = lane >> 2, q4 = lane & 3;
    const int wm = wid & 3, wn = wid >> 2;

    uint32_t a[4][4];
    {
        const uint32_t abase =
            su(sWc + (wm * 16 + (lane & 15)) * P72 + (lane >> 4) * 8);
#pragma unroll
        for (int kt = 0; kt < 4; kt++)
            LDSM4(a[kt][0], a[kt][1], a[kt][2], a[kt][3], abase + kt * 32);
    }

    const int r0_ = wm * 16 + g, r1_ = r0_ + 8;
    const float bc0 = bc[r0_], bc1 = bc[r1_];
    const int brow = lane & 7, bseg = lane >> 3;
    const __half2 hz = __float2half2_rn(0.f);

    for (int tile = 0; tile < 8; tile++) {
        const int base = blockIdx.y * 1024 + tile * 128;

        // phase A: y = v + q_sm @ kv (half2)
#pragma unroll
        for (int i = 0; i < 4; i++) {
            const int pl  = lane + 32 * i;
            const int pos = base + pl;
            const int l   = pos % 12;
            const size_t ib = ((size_t)b * NL_ + pos) * 64 + cg * 8;
            uint4 qr = *(const uint4*)&g_q16[ib];
            uint4 vr = *(const uint4*)&g_v16[ib];
            const __half2* qh2 = reinterpret_cast<const __half2*>(&qr);
            const __half2* vh2 = reinterpret_cast<const __half2*>(&vr);
            const __half* kvp = kvh + l * KVH_PITCH + cg * 64;

            __half2 accA[4] = {hz, hz, hz, hz};
            __half2 accB[4] = {hz, hz, hz, hz};
#pragma unroll
            for (int xp = 0; xp < 4; xp++) {
                const __half2 qlo = __low2half2(qh2[xp]);
                const __half2 qhi = __high2half2(qh2[xp]);
                uint4 ka = *(const uint4*)(kvp + (2 * xp) * 8);
                uint4 kb = *(const uint4*)(kvp + (2 * xp + 1) * 8);
                const __half2* ka2 = reinterpret_cast<const __half2*>(&ka);
                const __half2* kb2 = reinterpret_cast<const __half2*>(&kb);
                __half2* acc = (xp < 2) ? accA : accB;
#pragma unroll
                for (int j = 0; j < 4; j++) {
                    acc[j] = __hfma2(qlo, ka2[j], acc[j]);
                    acc[j] = __hfma2(qhi, kb2[j], acc[j]);
                }
            }
            uint4 u;
            __half2 y0 = __hadd2(__hadd2(accA[0], accB[0]), vh2[0]);
            __half2 y1 = __hadd2(__hadd2(accA[1], accB[1]), vh2[1]);
            __half2 y2 = __hadd2(__hadd2(accA[2], accB[2]), vh2[2]);
            __half2 y3 = __hadd2(__hadd2(accA[3], accB[3]), vh2[3]);
            u.x = h2u(y0); u.y = h2u(y1); u.z = h2u(y2); u.w = h2u(y3);
            *(uint4*)&ys[pl * P72 + cg * 8] = u;
        }
        __syncthreads();

        // phase B: Wc GEMM
        float acc[8][4];
#pragma unroll
        for (int nt = 0; nt < 8; nt++)
#pragma unroll
            for (int i = 0; i < 4; i++) acc[nt][i] = 0.f;

#pragma unroll
        for (int nt = 0; nt < 8; nt++) {
            const uint32_t bbase =
                su(ys + (wn * 64 + nt * 8 + brow) * P72 + bseg * 8);
#pragma unroll
            for (int kg = 0; kg < 2; kg++) {
                uint32_t r0, r1, r2, r3;
                LDSM4(r0, r1, r2, r3, bbase + kg * 64);
                mma16816(acc[nt], a[kg * 2],     r0, r1);
                mma16816(acc[nt], a[kg * 2 + 1], r2, r3);
            }
        }

        // fragment epilogue
#pragma unroll
        for (int nt = 0; nt < 8; nt++) {
            const int col = base + wn * 64 + nt * 8 + q4 * 2;
            const size_t w0 = (size_t)r0_ * NL_ + col;
            const size_t w1 = (size_t)r1_ * NL_ + col;
            const uint2 u0 = *(const uint2*)(g_wb + w0);
            const uint2 u1 = *(const uint2*)(g_wb + w1);
            const float2 wb00 = __half22float2(*reinterpret_cast<const __half2*>(&u0.x));
            const float2 wb01 = __half22float2(*reinterpret_cast<const __half2*>(&u0.y));
            const float2 wb10 = __half22float2(*reinterpret_cast<const __half2*>(&u1.x));
            const float2 wb11 = __half22float2(*reinterpret_cast<const __half2*>(&u1.y));
            float yf;
            float2 o0, o1;
            yf = acc[nt][0] + bc0; yf = yf > 0.f ? yf : 0.f;
            o0.x = yf * wb00.x + wb00.y + yf;
            yf = acc[nt][1] + bc0; yf = yf > 0.f ? yf : 0.f;
            o0.y = yf * wb01.x + wb01.y + yf;
            yf = acc[nt][2] + bc1; yf = yf > 0.f ? yf : 0.f;
            o1.x = yf * wb10.x + wb10.y + yf;
            yf = acc[nt][3] + bc1; yf = yf > 0.f ? yf : 0.f;
            o1.y = yf * wb11.x + wb11.y + yf;
            *(float2*)(out + ((size_t)b * 64) * NL_ + w0) = o0;
            *(float2*)(out + ((size_t)b * 64) * NL_ + w1) = o1;
        }
        __syncthreads();
    }
}

// ============================================================
extern "C" void kernel_launch(void* const* d_in, const int* in_sizes, int n_in,
                              void* d_out, int out_size) {
    const float* x      = (const float*)d_in[0];
    const float* wq     = (const float*)d_in[1];
    const float* bq     = (const float*)d_in[2];
    const float* wv     = (const float*)d_in[3];
    const float* bv     = (const float*)d_in[4];
    const float* wc     = (const float*)d_in[5];
    const float* bc     = (const float*)d_in[6];
    const float* memin  = (const float*)d_in[7];
    const float* weight = (const float*)d_in[8];
    const float* bias   = (const float*)d_in[9];
    // nv1/nv2 unused: row-sum of softmax == 1 -> attn_dyn = v.
    float* out = (float*)d_out;

    cudaFuncSetAttribute(k1_qv,  cudaFuncAttributeMaxDynamicSharedMemorySize, K1_SMEM);
    cudaFuncSetAttribute(k2_kv,  cudaFuncAttributeMaxDynamicSharedMemorySize, K2_SMEM);
    cudaFuncSetAttribute(k3_out, cudaFuncAttributeMaxDynamicSharedMemorySize, K3_SMEM);

    k0_keysm<<<(H_ * L_ * N_ + 255) / 256, 256>>>(memin);
    k0_wb<<<(D_ * NL_ / 4 + 255) / 256, 256>>>(weight, bias);

    dim3 g1(NL_ / 512, B_);
    k1_qv<<<g1, 256, K1_SMEM>>>(x, wq, bq, wv, bv);

    dim3 g2(H_, B_, K2SPLIT);
    k2_kv<<<g2, 192, K2_SMEM>>>();
    k2r_reduce<<<(B_ * H_ * L_ * 64 + 255) / 256, 256>>>();

    dim3 g3(B_, NL_ / 1024);
    k3_out<<<g3, 256, K3_SMEM>>>(wc, bc, out);
}

// round 17
// speedup vs baseline: 1.1149x; 1.1149x over previous
#include <cuda_runtime.h>
#include <cuda_fp16.h>
#include <math.h>
#include <stdint.h>

#define B_ 32
#define D_ 64
#define H_ 8
#define N_ 4096
#define L_ 12
#define DK_ 8
#define NL_ 49152
#define SCALE 0.3535533905932738f
#define CL2E 0.5101185143353461f   // SCALE * log2(e)
#define K2SPLIT 8

// ---- scratch ----
__device__ __half  g_q16[(size_t)B_ * NL_ * 64];
__device__ __half  g_v16[(size_t)B_ * NL_ * 64];
__device__ __half  g_keysm16[(size_t)H_ * L_ * N_ * DK_];
__device__ float   g_kv[B_ * H_ * L_ * DK_ * DK_];
__device__ float   g_kvp[K2SPLIT * B_ * H_ * L_ * DK_ * DK_];
__device__ __half2 g_wb[(size_t)D_ * NL_];

__device__ __forceinline__ void mma16816(float* c, const uint32_t* a,
                                         uint32_t b0, uint32_t b1) {
    asm volatile(
        "mma.sync.aligned.m16n8k16.row.col.f32.f16.f16.f32 "
        "{%0,%1,%2,%3}, {%4,%5,%6,%7}, {%8,%9}, {%0,%1,%2,%3};\n"
        : "+f"(c[0]), "+f"(c[1]), "+f"(c[2]), "+f"(c[3])
        : "r"(a[0]), "r"(a[1]), "r"(a[2]), "r"(a[3]), "r"(b0), "r"(b1));
}

__device__ __forceinline__ uint32_t su(const void* p) {
    return (uint32_t)__cvta_generic_to_shared(p);
}

__device__ __forceinline__ void cp16(uint32_t saddr, const void* gptr) {
    asm volatile("cp.async.cg.shared.global [%0], [%1], 16;\n"
                 :: "r"(saddr), "l"(gptr));
}
#define CP_COMMIT() asm volatile("cp.async.commit_group;\n" ::: "memory")
#define CP_WAIT1()  asm volatile("cp.async.wait_group 1;\n" ::: "memory")
#define CP_WAIT0()  asm volatile("cp.async.wait_group 0;\n" ::: "memory")

#define LDSM4(r0, r1, r2, r3, addr)                                        \
    asm volatile("ldmatrix.sync.aligned.m8n8.x4.shared.b16 {%0,%1,%2,%3}, [%4];" \
                 : "=r"(r0), "=r"(r1), "=r"(r2), "=r"(r3) : "r"(addr))

#define STSM4T(addr, r0, r1, r2, r3)                                       \
    asm volatile("stmatrix.sync.aligned.m8n8.x4.trans.shared.b16 [%0], {%1,%2,%3,%4};" \
                 :: "r"(addr), "r"(r0), "r"(r1), "r"(r2), "r"(r3))

__device__ __forceinline__ uint32_t h2u(__half2 h) {
    return *reinterpret_cast<uint32_t*>(&h);
}

// ============================================================
// K0 (merged prep): blocks [0, KB0): keysm softmax -> fp16
//                   blocks [KB0, KB0+KB1): (weight,bias) -> half2
// ============================================================
#define K0_B0 ((H_ * L_ * N_ + 255) / 256)        // 1536
#define K0_B1 ((D_ * NL_ / 4 + 255) / 256)        // 3072
__global__ void k0_prep(const float* __restrict__ memin,
                        const float* __restrict__ weight,
                        const float* __restrict__ bias) {
    if (blockIdx.x < K0_B0) {
        const int i = blockIdx.x * 256 + threadIdx.x;
        if (i >= H_ * L_ * N_) return;
        const float4 f0 = ((const float4*)memin)[(size_t)i * 2];
        const float4 f1 = ((const float4*)memin)[(size_t)i * 2 + 1];
        float v[8] = {f0.x, f0.y, f0.z, f0.w, f1.x, f1.y, f1.z, f1.w};
        float m = -1e30f;
#pragma unroll
        for (int k = 0; k < 8; k++) { v[k] *= SCALE; m = fmaxf(m, v[k]); }
        float s = 0.f;
#pragma unroll
        for (int k = 0; k < 8; k++) { v[k] = __expf(v[k] - m); s += v[k]; }
        const float inv = 1.f / s;
        uint4 u;
        u.x = h2u(__floats2half2_rn(v[0] * inv, v[1] * inv));
        u.y = h2u(__floats2half2_rn(v[2] * inv, v[3] * inv));
        u.z = h2u(__floats2half2_rn(v[4] * inv, v[5] * inv));
        u.w = h2u(__floats2half2_rn(v[6] * inv, v[7] * inv));
        ((uint4*)g_keysm16)[i] = u;
    } else {
        const int i = (blockIdx.x - K0_B0) * 256 + threadIdx.x;
        if (i >= D_ * NL_ / 4) return;
        const float4 w = ((const float4*)weight)[i];
        const float4 bi = ((const float4*)bias)[i];
        uint4 u;
        u.x = h2u(__floats2half2_rn(w.x, bi.x));
        u.y = h2u(__floats2half2_rn(w.y, bi.y));
        u.z = h2u(__floats2half2_rn(w.z, bi.z));
        u.w = h2u(__floats2half2_rn(w.w, bi.w));
        ((uint4*)g_wb)[i] = u;
    }
}

// ============================================================
// K1 (HMMA+LDSM+STSM, 4 tiles/block): [q;v] = [Wq;Wv] @ x  (R14)
// ============================================================
#define P72 72
#define QVP 136
#define K1_XS_OFF  (128 * P72 * 2)
#define K1_SQV_OFF (K1_XS_OFF + 128 * P72 * 2)
#define K1_SMEM    (K1_SQV_OFF + 128 * QVP * 2)
__global__ __launch_bounds__(256, 3)
void k1_qv(const float* __restrict__ x,  const float* __restrict__ wq,
           const float* __restrict__ bq, const float* __restrict__ wv,
           const float* __restrict__ bv) {
    extern __shared__ char sm1[];
    __half* sW  = (__half*)sm1;
    __half* xs  = (__half*)(sm1 + K1_XS_OFF);
    __half* sQV = (__half*)(sm1 + K1_SQV_OFF);

    const int t = threadIdx.x;
    const int b = blockIdx.y;

    for (int i = t; i < 512; i += 256) {
        const int row = i >> 3, seg = i & 7;
        const float4 f0 = *(const float4*)(wq + row * 64 + seg * 8);
        const float4 f1 = *(const float4*)(wq + row * 64 + seg * 8 + 4);
        uint4 u;
        u.x = h2u(__floats2half2_rn(f0.x, f0.y));
        u.y = h2u(__floats2half2_rn(f0.z, f0.w));
        u.z = h2u(__floats2half2_rn(f1.x, f1.y));
        u.w = h2u(__floats2half2_rn(f1.z, f1.w));
        *(uint4*)&sW[row * P72 + seg * 8] = u;
        const float4 g0 = *(const float4*)(wv + row * 64 + seg * 8);
        const float4 g1 = *(const float4*)(wv + row * 64 + seg * 8 + 4);
        u.x = h2u(__floats2half2_rn(g0.x, g0.y));
        u.y = h2u(__floats2half2_rn(g0.z, g0.w));
        u.z = h2u(__floats2half2_rn(g1.x, g1.y));
        u.w = h2u(__floats2half2_rn(g1.z, g1.w));
        *(uint4*)&sW[(64 + row) * P72 + seg * 8] = u;
    }

    const int wid = t >> 5, lane = t & 31;
    const int cg = wid;

    float bqC[8];
    __half2 bv2[4];
#pragma unroll
    for (int j = 0; j < 8; j++) bqC[j] = bq[cg * 8 + j] * CL2E;
#pragma unroll
    for (int j = 0; j < 4; j++)
        bv2[j] = __floats2half2_rn(bv[cg * 8 + 2 * j], bv[cg * 8 + 2 * j + 1]);
    const __half2 hzero = __float2half2_rn(0.f);

    const int mat = lane >> 3, mrow = lane & 7;
    const uint32_t stbase =
        su(sQV + ((mat >> 1) * 8 + mrow) * QVP + wid * 16 + (mat & 1) * 8);
    const int brow = lane & 7, bseg = lane >> 3;

    bool haveA = false;
    uint32_t a[4][4];

    for (int tile = 0; tile < 4; tile++) {
        const int base = blockIdx.x * 512 + tile * 128;

        {
            const int pos = t & 127;
            const int d0  = (t >> 7) * 32;
            const float* xb = x + (size_t)b * D_ * NL_ + base + pos;
            uint32_t pk[16];
#pragma unroll 4
            for (int dd = 0; dd < 32; dd += 2) {
                float x0 = xb[(size_t)(d0 + dd) * NL_];
                float x1 = xb[(size_t)(d0 + dd + 1) * NL_];
                pk[dd >> 1] = h2u(__floats2half2_rn(x0, x1));
            }
            uint4* dst = (uint4*)&xs[pos * P72 + d0];
#pragma unroll
            for (int s = 0; s < 4; s++)
                dst[s] = make_uint4(pk[4*s], pk[4*s+1], pk[4*s+2], pk[4*s+3]);
        }
        __syncthreads();

        if (!haveA) {
            const uint32_t abase =
                su(sW + (wid * 16 + (lane & 15)) * P72 + (lane >> 4) * 8);
#pragma unroll
            for (int kt = 0; kt < 4; kt++)
                LDSM4(a[kt][0], a[kt][1], a[kt][2], a[kt][3], abase + kt * 32);
            haveA = true;
        }

#pragma unroll
        for (int pass = 0; pass < 2; pass++) {
            float acc[8][4];
#pragma unroll
            for (int nt = 0; nt < 8; nt++)
#pragma unroll
                for (int i = 0; i < 4; i++) acc[nt][i] = 0.f;

#pragma unroll
            for (int nt = 0; nt < 8; nt++) {
                const int ntg = pass * 8 + nt;
                const uint32_t bbase = su(xs + (ntg * 8 + brow) * P72 + bseg * 8);
#pragma unroll
                for (int kg = 0; kg < 2; kg++) {
                    uint32_t r0, r1, r2, r3;
                    LDSM4(r0, r1, r2, r3, bbase + kg * 64);
                    mma16816(acc[nt], a[kg * 2],     r0, r1);
                    mma16816(acc[nt], a[kg * 2 + 1], r2, r3);
                }
            }
#pragma unroll
            for (int j = 0; j < 4; j++) {
                const int nt0 = 2 * j;
                const uint32_t addr = stbase + (uint32_t)((pass * 8 + nt0) * 8 * QVP * 2);
                const uint32_t r0 = h2u(__floats2half2_rn(acc[nt0][0],     acc[nt0][1]));
                const uint32_t r1 = h2u(__floats2half2_rn(acc[nt0][2],     acc[nt0][3]));
                const uint32_t r2 = h2u(__floats2half2_rn(acc[nt0+1][0], acc[nt0+1][1]));
                const uint32_t r3 = h2u(__floats2half2_rn(acc[nt0+1][2], acc[nt0+1][3]));
                STSM4T(addr, r0, r1, r2, r3);
            }
        }
        __syncthreads();

#pragma unroll
        for (int i = 0; i < 4; i++) {
            const int pos = lane + 32 * i;
            const __half* row = sQV + pos * QVP;
            uint4 qraw = *(const uint4*)(row + cg * 8);
            uint4 vraw = *(const uint4*)(row + 64 + cg * 8);

            float e[8];
            {
                float2 f;
                f = __half22float2(*reinterpret_cast<__half2*>(&qraw.x)); e[0]=f.x; e[1]=f.y;
                f = __half22float2(*reinterpret_cast<__half2*>(&qraw.y)); e[2]=f.x; e[3]=f.y;
                f = __half22float2(*reinterpret_cast<__half2*>(&qraw.z)); e[4]=f.x; e[5]=f.y;
                f = __half22float2(*reinterpret_cast<__half2*>(&qraw.w)); e[6]=f.x; e[7]=f.y;
            }
            float s = 0.f;
#pragma unroll
            for (int j = 0; j < 8; j++) {
                float aa = fmaf(e[j], CL2E, bqC[j]);
                aa = fmaxf(aa, 0.f);
                e[j] = exp2f(aa);
                s += e[j];
            }
            const float inv = __fdividef(1.f, s);

            uint4 qu, vu;
            qu.x = h2u(__floats2half2_rn(e[0] * inv, e[1] * inv));
            qu.y = h2u(__floats2half2_rn(e[2] * inv, e[3] * inv));
            qu.z = h2u(__floats2half2_rn(e[4] * inv, e[5] * inv));
            qu.w = h2u(__floats2half2_rn(e[6] * inv, e[7] * inv));

            vu.x = h2u(__hmax2(__hadd2(*reinterpret_cast<__half2*>(&vraw.x), bv2[0]), hzero));
            vu.y = h2u(__hmax2(__hadd2(*reinterpret_cast<__half2*>(&vraw.y), bv2[1]), hzero));
            vu.z = h2u(__hmax2(__hadd2(*reinterpret_cast<__half2*>(&vraw.z), bv2[2]), hzero));
            vu.w = h2u(__hmax2(__hadd2(*reinterpret_cast<__half2*>(&vraw.w), bv2[3]), hzero));

            const size_t ob = ((size_t)b * NL_ + base + pos) * 64 + cg * 8;
            *(uint4*)&g_q16[ob] = qu;
            *(uint4*)&g_v16[ob] = vu;
        }
        __syncthreads();
    }
}

// ============================================================
// K2: split-K (8) cp.async double-buffered (R14: occupancy 3, 96 regs).
// ============================================================
#define K2_NCH 64
#define K2_KBUF 6144
#define K2_VBUF 6240
#define K2_V_OFF (2 * K2_KBUF)
#define K2_SMEM ((2 * K2_KBUF + 2 * K2_VBUF) * 2)
__global__ __launch_bounds__(192, 3)
void k2_kv() {
    extern __shared__ __half sm2[];
    __half* sK = sm2;
    __half* sV = sm2 + K2_V_OFF;

    const int t = threadIdx.x;
    const int h = blockIdx.x;
    const int b = blockIdx.y;
    const int sp = blockIdx.z;
    const int s = t & 15;
    const int l = t >> 4;

    const int nlo = sp * (N_ / K2SPLIT);
    const int nchunks = (N_ / K2SPLIT) / K2_NCH;

    int kll[4], knn[4], vll[4], vnn[4];
#pragma unroll
    for (int j = 0; j < 4; j++) {
        const int i = t + j * 192;
        kll[j] = i >> 6;  knn[j] = i & 63;
        vll[j] = i % 12;  vnn[j] = i / 12;
    }

    auto prefetch = [&](int n0, int buf) {
#pragma unroll
        for (int j = 0; j < 4; j++) {
            cp16(su(sK + buf * K2_KBUF + (kll[j] * 64 + knn[j]) * 8),
                 &g_keysm16[((size_t)(h * 12 + kll[j]) * N_ + n0 + knn[j]) * 8]);
        }
#pragma unroll
        for (int j = 0; j < 4; j++) {
            const int pos = (n0 + vnn[j]) * 12 + vll[j];
            cp16(su(sV + buf * K2_VBUF + (vll[j] * 65 + vnn[j]) * 8),
                 &g_v16[((size_t)b * NL_ + pos) * 64 + h * 8]);
        }
    };

    float acc[8][8];
#pragma unroll
    for (int xx = 0; xx < 8; xx++)
#pragma unroll
        for (int yy = 0; yy < 8; yy++) acc[xx][yy] = 0.f;

    prefetch(nlo, 0);
    CP_COMMIT();

    for (int c = 0; c < nchunks; c++) {
        if (c + 1 < nchunks) {
            prefetch(nlo + (c + 1) * K2_NCH, (c + 1) & 1);
            CP_COMMIT();
            CP_WAIT1();
        } else {
            CP_WAIT0();
        }
        __syncthreads();

        const __half* bK = sK + (c & 1) * K2_KBUF;
        const __half* bV = sV + (c & 1) * K2_VBUF;

#pragma unroll
        for (int p = 0; p < 4; p++) {
            const int nn = s + 16 * p;
            float kf[8], vf[8];
            uint4 ku = *(const uint4*)(bK + (l * 64 + nn) * 8);
            uint4 vu = *(const uint4*)(bV + (l * 65 + nn) * 8);
            {
                float2 f;
                f = __half22float2(*reinterpret_cast<__half2*>(&ku.x)); kf[0]=f.x; kf[1]=f.y;
                f = __half22float2(*reinterpret_cast<__half2*>(&ku.y)); kf[2]=f.x; kf[3]=f.y;
                f = __half22float2(*reinterpret_cast<__half2*>(&ku.z)); kf[4]=f.x; kf[5]=f.y;
                f = __half22float2(*reinterpret_cast<__half2*>(&ku.w)); kf[6]=f.x; kf[7]=f.y;
                f = __half22float2(*reinterpret_cast<__half2*>(&vu.x)); vf[0]=f.x; vf[1]=f.y;
                f = __half22float2(*reinterpret_cast<__half2*>(&vu.y)); vf[2]=f.x; vf[3]=f.y;
                f = __half22float2(*reinterpret_cast<__half2*>(&vu.z)); vf[4]=f.x; vf[5]=f.y;
                f = __half22float2(*reinterpret_cast<__half2*>(&vu.w)); vf[6]=f.x; vf[7]=f.y;
            }
#pragma unroll
            for (int xx = 0; xx < 8; xx++)
#pragma unroll
                for (int yy = 0; yy < 8; yy++) acc[xx][yy] += kf[xx] * vf[yy];
        }
        __syncthreads();
    }

#pragma unroll
    for (int xx = 0; xx < 8; xx++)
#pragma unroll
        for (int yy = 0; yy < 8; yy++) {
            float v_ = acc[xx][yy];
            v_ += __shfl_xor_sync(0xffffffffu, v_, 1);
            v_ += __shfl_xor_sync(0xffffffffu, v_, 2);
            v_ += __shfl_xor_sync(0xffffffffu, v_, 4);
            v_ += __shfl_xor_sync(0xffffffffu, v_, 8);
            acc[xx][yy] = v_;
        }
    if (s == 0) {
        float* dst = g_kvp + (size_t)sp * (B_ * H_ * L_ * 64) +
                     (((size_t)(b * 8 + h) * 12 + l) * 64);
#pragma unroll
        for (int xx = 0; xx < 8; xx++)
#pragma unroll
            for (int yy = 0; yy < 8; yy++) dst[xx * 8 + yy] = acc[xx][yy];
    }
}

__global__ void k2r_reduce() {
    const int i = blockIdx.x * 256 + threadIdx.x;
    const int S = B_ * H_ * L_ * 64;
    if (i >= S) return;
    float s = 0.f;
#pragma unroll
    for (int sp = 0; sp < K2SPLIT; sp++) s += g_kvp[i + (size_t)sp * S];
    g_kv[i] = s;
}

// ============================================================
// K3 (HMMA, 4 tiles/block): phase A half2; wb16 epilogue.  (R14)
// ============================================================
#define KVH_PITCH 552
#define K3_KVH_OFF (64 * P72 * 2)
#define K3_YS_OFF  (K3_KVH_OFF + 12 * KVH_PITCH * 2)
#define K3_SMEM    (K3_YS_OFF + 128 * P72 * 2)
__global__ __launch_bounds__(256, 3)
void k3_out(const float* __restrict__ wc, const float* __restrict__ bc,
            float* __restrict__ out) {
    extern __shared__ char sm3[];
    __half* sWc = (__half*)sm3;
    __half* kvh = (__half*)(sm3 + K3_KVH_OFF);
    __half* ys  = (__half*)(sm3 + K3_YS_OFF);

    const int t = threadIdx.x;
    const int b = blockIdx.x;

    for (int i = t; i < 512; i += 256) {
        const int row = i >> 3, seg = i & 7;
        const float4 f0 = *(const float4*)(wc + row * 64 + seg * 8);
        const float4 f1 = *(const float4*)(wc + row * 64 + seg * 8 + 4);
        uint4 u;
        u.x = h2u(__floats2half2_rn(f0.x, f0.y));
        u.y = h2u(__floats2half2_rn(f0.z, f0.w));
        u.z = h2u(__floats2half2_rn(f1.x, f1.y));
        u.w = h2u(__floats2half2_rn(f1.z, f1.w));
        *(uint4*)&sWc[row * P72 + seg * 8] = u;
    }
    for (int i = t; i < 3072; i += 256) {
        const int idx = i * 2;
        const float2 f = *(const float2*)(g_kv + (size_t)b * 6144 + idx);
        const int h = idx / 768, r = idx % 768, l = r >> 6, xy = r & 63;
        *(__half2*)&kvh[l * KVH_PITCH + h * 64 + xy] = __floats2half2_rn(f.x, f.y);
    }
    __syncthreads();

    const int lane = t & 31, cg = t >> 5;
    const int wid = t >> 5;
    const int g = lane >> 2, q4 = lane & 3;
    const int wm = wid & 3, wn = wid >> 2;

    uint32_t a[4][4];
    {
        const uint32_t abase =
            su(sWc + (wm * 16 + (lane & 15)) * P72 + (lane >> 4) * 8);
#pragma unroll
        for (int kt = 0; kt < 4; kt++)
            LDSM4(a[kt][0], a[kt][1], a[kt][2], a[kt][3], abase + kt * 32);
    }

    const int r0_ = wm * 16 + g, r1_ = r0_ + 8;
    const float bc0 = bc[r0_], bc1 = bc[r1_];
    const int brow = lane & 7, bseg = lane >> 3;
    const __half2 hz = __float2half2_rn(0.f);

    for (int tile = 0; tile < 4; tile++) {
        const int base = blockIdx.y * 512 + tile * 128;

#pragma unroll
        for (int i = 0; i < 4; i++) {
            const int pl  = lane + 32 * i;
            const int pos = base + pl;
            const int l   = pos % 12;
            const size_t ib = ((size_t)b * NL_ + pos) * 64 + cg * 8;
            uint4 qr = *(const uint4*)&g_q16[ib];
            uint4 vr = *(const uint4*)&g_v16[ib];
            const __half2* qh2 = reinterpret_cast<const __half2*>(&qr);
            const __half2* vh2 = reinterpret_cast<const __half2*>(&vr);
            const __half* kvp = kvh + l * KVH_PITCH + cg * 64;

            __half2 accA[4] = {hz, hz, hz, hz};
            __half2 accB[4] = {hz, hz, hz, hz};
#pragma unroll
            for (int xp = 0; xp < 4; xp++) {
                const __half2 qlo = __low2half2(qh2[xp]);
                const __half2 qhi = __high2half2(qh2[xp]);
                uint4 ka = *(const uint4*)(kvp + (2 * xp) * 8);
                uint4 kb = *(const uint4*)(kvp + (2 * xp + 1) * 8);
                const __half2* ka2 = reinterpret_cast<const __half2*>(&ka);
                const __half2* kb2 = reinterpret_cast<const __half2*>(&kb);
                __half2* acc = (xp < 2) ? accA : accB;
#pragma unroll
                for (int j = 0; j < 4; j++) {
                    acc[j] = __hfma2(qlo, ka2[j], acc[j]);
                    acc[j] = __hfma2(qhi, kb2[j], acc[j]);
                }
            }
            uint4 u;
            __half2 y0 = __hadd2(__hadd2(accA[0], accB[0]), vh2[0]);
            __half2 y1 = __hadd2(__hadd2(accA[1], accB[1]), vh2[1]);
            __half2 y2 = __hadd2(__hadd2(accA[2], accB[2]), vh2[2]);
            __half2 y3 = __hadd2(__hadd2(accA[3], accB[3]), vh2[3]);
            u.x = h2u(y0); u.y = h2u(y1); u.z = h2u(y2); u.w = h2u(y3);
            *(uint4*)&ys[pl * P72 + cg * 8] = u;
        }
        __syncthreads();

        float acc[8][4];
#pragma unroll
        for (int nt = 0; nt < 8; nt++)
#pragma unroll
            for (int i = 0; i < 4; i++) acc[nt][i] = 0.f;

#pragma unroll
        for (int nt = 0; nt < 8; nt++) {
            const uint32_t bbase =
                su(ys + (wn * 64 + nt * 8 + brow) * P72 + bseg * 8);
#pragma unroll
            for (int kg = 0; kg < 2; kg++) {
                uint32_t r0, r1, r2, r3;
                LDSM4(r0, r1, r2, r3, bbase + kg * 64);
                mma16816(acc[nt], a[kg * 2],     r0, r1);
                mma16816(acc[nt], a[kg * 2 + 1], r2, r3);
            }
        }

#pragma unroll
        for (int nt = 0; nt < 8; nt++) {
            const int col = base + wn * 64 + nt * 8 + q4 * 2;
            const size_t w0 = (size_t)r0_ * NL_ + col;
            const size_t w1 = (size_t)r1_ * NL_ + col;
            const uint2 u0 = *(const uint2*)(g_wb + w0);
            const uint2 u1 = *(const uint2*)(g_wb + w1);
            const float2 wb00 = __half22float2(*reinterpret_cast<const __half2*>(&u0.x));
            const float2 wb01 = __half22float2(*reinterpret_cast<const __half2*>(&u0.y));
            const float2 wb10 = __half22float2(*reinterpret_cast<const __half2*>(&u1.x));
            const float2 wb11 = __half22float2(*reinterpret_cast<const __half2*>(&u1.y));
            float yf;
            float2 o0, o1;
            yf = acc[nt][0] + bc0; yf = yf > 0.f ? yf : 0.f;
            o0.x = yf * wb00.x + wb00.y + yf;
            yf = acc[nt][1] + bc0; yf = yf > 0.f ? yf : 0.f;
            o0.y = yf * wb01.x + wb01.y + yf;
            yf = acc[nt][2] + bc1; yf = yf > 0.f ? yf : 0.f;
            o1.x = yf * wb10.x + wb10.y + yf;
            yf = acc[nt][3] + bc1; yf = yf > 0.f ? yf : 0.f;
            o1.y = yf * wb11.x + wb11.y + yf;
            *(float2*)(out + ((size_t)b * 64) * NL_ + w0) = o0;
            *(float2*)(out + ((size_t)b * 64) * NL_ + w1) = o1;
        }
        __syncthreads();
    }
}

// ============================================================
extern "C" void kernel_launch(void* const* d_in, const int* in_sizes, int n_in,
                              void* d_out, int out_size) {
    const float* x      = (const float*)d_in[0];
    const float* wq     = (const float*)d_in[1];
    const float* bq     = (const float*)d_in[2];
    const float* wv     = (const float*)d_in[3];
    const float* bv     = (const float*)d_in[4];
    const float* wc     = (const float*)d_in[5];
    const float* bc     = (const float*)d_in[6];
    const float* memin  = (const float*)d_in[7];
    const float* weight = (const float*)d_in[8];
    const float* bias   = (const float*)d_in[9];
    // nv1/nv2 unused: row-sum of softmax == 1 -> attn_dyn = v.
    float* out = (float*)d_out;

    cudaFuncSetAttribute(k1_qv,  cudaFuncAttributeMaxDynamicSharedMemorySize, K1_SMEM);
    cudaFuncSetAttribute(k2_kv,  cudaFuncAttributeMaxDynamicSharedMemorySize, K2_SMEM);
    cudaFuncSetAttribute(k3_out, cudaFuncAttributeMaxDynamicSharedMemorySize, K3_SMEM);

    k0_prep<<<K0_B0 + K0_B1, 256>>>(memin, weight, bias);

    dim3 g1(NL_ / 512, B_);
    k1_qv<<<g1, 256, K1_SMEM>>>(x, wq, bq, wv, bv);

    dim3 g2(H_, B_, K2SPLIT);
    k2_kv<<<g2, 192, K2_SMEM>>>();
    k2r_reduce<<<(B_ * H_ * L_ * 64 + 255) / 256, 256>>>();

    dim3 g3(B_, NL_ / 512);
    k3_out<<<g3, 256, K3_SMEM>>>(wc, bc, out);
}